// round 16
// baseline (speedup 1.0000x reference)
#include <cuda_runtime.h>
#include <cuda_fp16.h>
#include <cstdint>

#define MDIM 8192
#define NDIM 1024
#define CHUNK 4096
#define NCH (MDIM / CHUNK)

// ---------------------------------------------------------------------------
// Static scratch (no allocation allowed). Total ~268 MB.
// ---------------------------------------------------------------------------
__device__ __half g_xh[(size_t)MDIM * NDIM], g_xl[(size_t)MDIM * NDIM];
__device__ __half g_Wqh[(size_t)NDIM * NDIM], g_Wql[(size_t)NDIM * NDIM];
__device__ __half g_Wkh[(size_t)NDIM * NDIM], g_Wkl[(size_t)NDIM * NDIM];
__device__ __half g_Wvh[(size_t)NDIM * NDIM], g_Wvl[(size_t)NDIM * NDIM];
__device__ __half g_Qh[(size_t)MDIM * NDIM], g_Ql[(size_t)MDIM * NDIM];
__device__ __half g_Kh[(size_t)MDIM * NDIM], g_Kl[(size_t)MDIM * NDIM];
__device__ __half g_Vth[(size_t)NDIM * MDIM], g_Vtl[(size_t)NDIM * MDIM]; // V^T
__device__ float g_Sc[(size_t)CHUNK * MDIM];

// ---------------------------------------------------------------------------
// Portable (sm_80+) tensor-core primitives — NO tcgen05 (harness targets base
// sm_100, which rejects arch-specific instructions).
// ---------------------------------------------------------------------------
__device__ __forceinline__ uint32_t smem_u32(const void* p) {
    uint32_t a;
    asm("{ .reg .u64 t; cvta.to.shared.u64 t, %1; cvt.u32.u64 %0, t; }"
        : "=r"(a) : "l"(p));
    return a;
}

__device__ __forceinline__ void ldsm_x4(uint32_t* r, uint32_t addr) {
    asm volatile("ldmatrix.sync.aligned.m8n8.x4.shared.b16 {%0,%1,%2,%3}, [%4];"
                 : "=r"(r[0]), "=r"(r[1]), "=r"(r[2]), "=r"(r[3]) : "r"(addr));
}

__device__ __forceinline__ void mma_f16(float* d, const uint32_t* a,
                                        uint32_t b0, uint32_t b1) {
    asm volatile(
        "mma.sync.aligned.m16n8k16.row.col.f32.f16.f16.f32 "
        "{%0,%1,%2,%3}, {%4,%5,%6,%7}, {%8,%9}, {%0,%1,%2,%3};"
        : "+f"(d[0]), "+f"(d[1]), "+f"(d[2]), "+f"(d[3])
        : "r"(a[0]), "r"(a[1]), "r"(a[2]), "r"(a[3]), "r"(b0), "r"(b1));
}

#define CP_ASYNC16(dst, src) \
    asm volatile("cp.async.cg.shared.global [%0], [%1], 16;" \
                 :: "r"(dst), "l"(src) : "memory")
#define CP_COMMIT() asm volatile("cp.async.commit_group;" ::: "memory")
#define CP_WAIT0()  asm volatile("cp.async.wait_group 0;" ::: "memory")

// ---------------------------------------------------------------------------
// GEMM (NT), fp16 split-precision, fp32 accumulate via mma.sync.m16n8k16.
//   NPROD==3: C = Ahi·Bhi^T + Ahi·Blo^T + Alo·Bhi^T  (err ~2^-22)
//   NPROD==2: C = Ahi·Bhi^T + Alo·Bhi^T              (B hi-only, err ~2^-12)
//             (Blo never loaded: 3 tiles per stage instead of 4)
// Inner loop: product-pass-outermost ordering. All fragments for a k16 step
// are loaded first, then 2-3 full passes over the 16 warp positions. Adjacent
// MMAs always target DIFFERENT accumulators (same-d reuse distance 16) so the
// tensor pipe is not stalled on accumulator RAW latency. Per-accumulator
// addition order is unchanged vs previous rounds (bitwise-identical results).
//   EPI 0: Cf[row*Csr+col] = acc * alpha
//   EPI 1: v = acc + bias[col]; Chi/Clo[row*Cosr+col] = hi/lo(v)
//   EPI 2: v = acc + bias[col]; Chi/Clo[col*Cosr+row] = hi/lo(v)  (transposed)
// BM=BN=128, BK=32, 256 threads (8 warps of 32x64), 2-stage cp.async pipeline,
// 2 CTAs/SM.
// ---------------------------------------------------------------------------
constexpr int BM = 128, BN = 128, BK = 32;
constexpr int TSTR = 80;                  // smem bytes per tile row (bank-safe)
constexpr int TILE_B = 128 * TSTR;        // 10240 B per tile
constexpr int STAGE_B = 4 * TILE_B;       // Ahi, Alo, Bhi, (Blo)
constexpr int SMEM_BYTES = 2 * STAGE_B;   // 81920 B; epilogue staging reuses it

template <int EPI, int NPROD>
__global__ __launch_bounds__(256, 2) void gemm_mma(
    const __half* __restrict__ Ahi, const __half* __restrict__ Alo, size_t Asr,
    const __half* __restrict__ Bhi, const __half* __restrict__ Blo, size_t Bsr,
    int Kdim, float alpha,
    float* __restrict__ Cf, size_t Csr,
    __half* __restrict__ Chi, __half* __restrict__ Clo, size_t Cosr,
    const float* __restrict__ bias)
{
    extern __shared__ char smem[];
    const uint32_t sb = smem_u32(smem);
    const int tid = threadIdx.x, lane = tid & 31, wid = tid >> 5;
    const int bm = blockIdx.y * BM, bn = blockIdx.x * BN;
    const int wm = (wid & 3) * 32, wn = (wid >> 2) * 64;

    float acc[2][8][4];
#pragma unroll
    for (int i = 0; i < 2; i++)
#pragma unroll
        for (int j = 0; j < 8; j++)
#pragma unroll
            for (int q = 0; q < 4; q++) acc[i][j][q] = 0.f;

    const int S = Kdim / BK;

    // Stage loader: 3 or 4 tiles x 128 rows x 64B; 512 x 16B chunks per tile.
#define LOAD_STAGE(stg_u32, k0)                                                 \
    do {                                                                        \
        _Pragma("unroll")                                                       \
        for (int it = 0; it < 2; it++) {                                        \
            const int idx = tid + it * 256;                                     \
            const int r = idx >> 2, c = idx & 3;                                \
            const char* ga = (const char*)(Ahi + (size_t)(bm + r) * Asr + (k0)) + c * 16; \
            const char* gb = (const char*)(Alo + (size_t)(bm + r) * Asr + (k0)) + c * 16; \
            const char* gc = (const char*)(Bhi + (size_t)(bn + r) * Bsr + (k0)) + c * 16; \
            const uint32_t o = (uint32_t)(r * TSTR + c * 16);                   \
            CP_ASYNC16((stg_u32) + 0 * TILE_B + o, ga);                         \
            CP_ASYNC16((stg_u32) + 1 * TILE_B + o, gb);                         \
            CP_ASYNC16((stg_u32) + 2 * TILE_B + o, gc);                         \
            if (NPROD == 3) {                                                   \
                const char* gd = (const char*)(Blo + (size_t)(bn + r) * Bsr + (k0)) + c * 16; \
                CP_ASYNC16((stg_u32) + 3 * TILE_B + o, gd);                     \
            }                                                                   \
        }                                                                       \
    } while (0)

    LOAD_STAGE(sb, 0);
    CP_COMMIT();

    // ldmatrix lane decomposition: 4 groups of 8 lanes -> 4 8x8 tiles
    const int lr = lane & 7;
    const int lg1 = (lane >> 3) & 1;   // +8 rows
    const int lg2 = lane >> 4;         // +8 cols (16 bytes)

    for (int s = 0; s < S; s++) {
        CP_WAIT0();
        __syncthreads();
        const uint32_t sc = sb + (uint32_t)((s & 1) * STAGE_B);
        if (s + 1 < S) {
            const uint32_t sn = sb + (uint32_t)(((s + 1) & 1) * STAGE_B);
            LOAD_STAGE(sn, (s + 1) * BK);
            CP_COMMIT();
        }

#pragma unroll
        for (int ks = 0; ks < 2; ks++) {
            const int kb = ks * 32;    // byte offset of this k16 step

            // ---- Load ALL fragments for this k16 step ----
            uint32_t ah[2][4], al[2][4], bh[4][4], bl[4][4];
#pragma unroll
            for (int mt = 0; mt < 2; mt++) {
                const uint32_t aaddr = sc +
                    (uint32_t)((wm + mt * 16 + lr + lg1 * 8) * TSTR + kb + lg2 * 16);
                ldsm_x4(ah[mt], aaddr);
                ldsm_x4(al[mt], aaddr + TILE_B);
            }
#pragma unroll
            for (int nt = 0; nt < 4; nt++) {
                const uint32_t baddr = sc + 2 * TILE_B +
                    (uint32_t)((wn + nt * 16 + lr + lg1 * 8) * TSTR + kb + lg2 * 16);
                ldsm_x4(bh[nt], baddr);
                if (NPROD == 3) ldsm_x4(bl[nt], baddr + TILE_B);
            }

            // ---- Pass 0: hi*hi (16 independent accumulators) ----
#pragma unroll
            for (int nt = 0; nt < 4; nt++)
#pragma unroll
                for (int mt = 0; mt < 2; mt++)
#pragma unroll
                    for (int h = 0; h < 2; h++)
                        mma_f16(acc[mt][nt * 2 + h], ah[mt], bh[nt][h], bh[nt][2 + h]);

            // ---- Pass 1: hi*lo (NPROD==3 only) ----
            if (NPROD == 3) {
#pragma unroll
                for (int nt = 0; nt < 4; nt++)
#pragma unroll
                    for (int mt = 0; mt < 2; mt++)
#pragma unroll
                        for (int h = 0; h < 2; h++)
                            mma_f16(acc[mt][nt * 2 + h], ah[mt], bl[nt][h], bl[nt][2 + h]);
            }

            // ---- Pass 2: lo*hi ----
#pragma unroll
            for (int nt = 0; nt < 4; nt++)
#pragma unroll
                for (int mt = 0; mt < 2; mt++)
#pragma unroll
                    for (int h = 0; h < 2; h++)
                        mma_f16(acc[mt][nt * 2 + h], al[mt], bh[nt][h], bh[nt][2 + h]);
        }
        __syncthreads();
    }

    // ---- Epilogue: regs -> padded SMEM staging -> coalesced global stores ----
    float* stg = (float*)smem;   // [128][129] fp32 (tile buffers now dead)
#pragma unroll
    for (int mt = 0; mt < 2; mt++)
#pragma unroll
        for (int nf = 0; nf < 8; nf++) {
            const int r0 = wm + mt * 16 + (lane >> 2);
            const int cl = wn + nf * 8 + (lane & 3) * 2;
            float v0 = acc[mt][nf][0], v1 = acc[mt][nf][1];
            float v2 = acc[mt][nf][2], v3 = acc[mt][nf][3];
            if (EPI == 0) {
                v0 *= alpha; v1 *= alpha; v2 *= alpha; v3 *= alpha;
            } else {
                const float b0 = bias[bn + cl], b1 = bias[bn + cl + 1];
                v0 += b0; v1 += b1; v2 += b0; v3 += b1;
            }
            stg[r0 * 129 + cl] = v0;
            stg[r0 * 129 + cl + 1] = v1;
            stg[(r0 + 8) * 129 + cl] = v2;
            stg[(r0 + 8) * 129 + cl + 1] = v3;
        }
    __syncthreads();

    if (EPI == 0) {
        for (int i = tid; i < BM * 32; i += 256) {
            const int r = i >> 5, q = (i & 31) * 4;
            float4 v;
            v.x = stg[r * 129 + q + 0];
            v.y = stg[r * 129 + q + 1];
            v.z = stg[r * 129 + q + 2];
            v.w = stg[r * 129 + q + 3];
            *(float4*)(Cf + (size_t)(bm + r) * Csr + bn + q) = v;
        }
    } else {
        for (int i = tid; i < BM * 16; i += 256) {
            const int a0 = i >> 4, g = (i & 15) * 8;
            alignas(16) __half hh[8], ll[8];
#pragma unroll
            for (int j = 0; j < 8; j++) {
                const float v = (EPI == 1) ? stg[a0 * 129 + g + j]
                                           : stg[(g + j) * 129 + a0];
                const __half h = __float2half(v);
                hh[j] = h;
                ll[j] = __float2half(v - __half2float(h));
            }
            const size_t off = (EPI == 1) ? ((size_t)(bm + a0) * Cosr + bn + g)
                                          : ((size_t)(bn + a0) * Cosr + bm + g);
            *(uint4*)(Chi + off) = *(const uint4*)hh;
            *(uint4*)(Clo + off) = *(const uint4*)ll;
        }
    }
#undef LOAD_STAGE
}

// ---------------------------------------------------------------------------
// Fused fp32 -> fp16 hi/lo split for x, Wq, Wk, Wv in ONE launch.
// ---------------------------------------------------------------------------
__global__ void split4_kernel(const float* __restrict__ x,
                              const float* __restrict__ wq,
                              const float* __restrict__ wk,
                              const float* __restrict__ wv,
                              __half* __restrict__ xh, __half* __restrict__ xl,
                              __half* __restrict__ qh, __half* __restrict__ ql,
                              __half* __restrict__ kh, __half* __restrict__ kl,
                              __half* __restrict__ vh, __half* __restrict__ vl)
{
    const size_t NX = (size_t)MDIM * NDIM;        // 8M
    const size_t NW = (size_t)NDIM * NDIM;        // 1M
    const size_t total = NX + 3 * NW;
    for (size_t i = (size_t)blockIdx.x * blockDim.x + threadIdx.x; i < total;
         i += (size_t)gridDim.x * blockDim.x) {
        const float* s; __half* h; __half* l; size_t j;
        if (i < NX)               { s = x;  h = xh; l = xl; j = i; }
        else if (i < NX + NW)     { s = wq; h = qh; l = ql; j = i - NX; }
        else if (i < NX + 2 * NW) { s = wk; h = kh; l = kl; j = i - NX - NW; }
        else                      { s = wv; h = vh; l = vl; j = i - NX - 2 * NW; }
        const float v = s[j];
        const __half hh = __float2half(v);
        h[j] = hh;
        l[j] = __float2half(v - __half2float(hh));
    }
}

// ---------------------------------------------------------------------------
// Row softmax over fp32 rows of length MDIM; writes P back IN PLACE as
// fp16 hi (first half of the row) + fp16 lo (second half). One block per row.
// ---------------------------------------------------------------------------
__global__ __launch_bounds__(256) void softmax_split_kernel(float* __restrict__ S)
{
    __shared__ float red[8];
    __shared__ float bcast;
    const int t = threadIdx.x;
    float* row = S + (size_t)blockIdx.x * MDIM;

    float v[32];
    float m = -1e30f;
#pragma unroll
    for (int i = 0; i < 32; i++) {
        v[i] = row[t + 256 * i];
        m = fmaxf(m, v[i]);
    }
#pragma unroll
    for (int o = 16; o; o >>= 1) m = fmaxf(m, __shfl_xor_sync(0xffffffffu, m, o));
    if ((t & 31) == 0) red[t >> 5] = m;
    __syncthreads();
    if (t < 32) {
        float mm = (t < 8) ? red[t] : -1e30f;
#pragma unroll
        for (int o = 4; o; o >>= 1) mm = fmaxf(mm, __shfl_xor_sync(0xffffffffu, mm, o));
        if (t == 0) bcast = mm;
    }
    __syncthreads();
    m = bcast;

    float ssum = 0.f;
    const float LOG2E = 1.4426950408889634f;
#pragma unroll
    for (int i = 0; i < 32; i++) {
        v[i] = exp2f((v[i] - m) * LOG2E);
        ssum += v[i];
    }
#pragma unroll
    for (int o = 16; o; o >>= 1) ssum += __shfl_xor_sync(0xffffffffu, ssum, o);
    __syncthreads();
    if ((t & 31) == 0) red[t >> 5] = ssum;
    __syncthreads();
    if (t < 32) {
        float ss = (t < 8) ? red[t] : 0.f;
#pragma unroll
        for (int o = 4; o; o >>= 1) ss += __shfl_xor_sync(0xffffffffu, ss, o);
        if (t == 0) bcast = ss;
    }
    __syncthreads();
    const float inv = 1.0f / bcast;

    __half* hrow = (__half*)row;
    __half* lrow = hrow + MDIM;
#pragma unroll
    for (int i = 0; i < 32; i++) {
        const float p = v[i] * inv;
        const __half h = __float2half(p);
        hrow[t + 256 * i] = h;
        lrow[t + 256 * i] = __float2half(p - __half2float(h));
    }
}

// ---------------------------------------------------------------------------
// Launch
// ---------------------------------------------------------------------------
extern "C" void kernel_launch(void* const* d_in, const int* in_sizes, int n_in,
                              void* d_out, int out_size)
{
    const float* x  = (const float*)d_in[0];
    const float* Wq = (const float*)d_in[1];
    const float* bq = (const float*)d_in[2];
    const float* Wk = (const float*)d_in[3];
    const float* bk = (const float*)d_in[4];
    const float* Wv = (const float*)d_in[5];
    const float* bv = (const float*)d_in[6];
    float* out = (float*)d_out;

    __half *xh, *xl, *Wqh, *Wql, *Wkh, *Wkl, *Wvh, *Wvl;
    __half *Qh, *Ql, *Kh, *Kl, *Vth, *Vtl;
    float* Sc;
    cudaGetSymbolAddress((void**)&xh, g_xh);   cudaGetSymbolAddress((void**)&xl, g_xl);
    cudaGetSymbolAddress((void**)&Wqh, g_Wqh); cudaGetSymbolAddress((void**)&Wql, g_Wql);
    cudaGetSymbolAddress((void**)&Wkh, g_Wkh); cudaGetSymbolAddress((void**)&Wkl, g_Wkl);
    cudaGetSymbolAddress((void**)&Wvh, g_Wvh); cudaGetSymbolAddress((void**)&Wvl, g_Wvl);
    cudaGetSymbolAddress((void**)&Qh, g_Qh);   cudaGetSymbolAddress((void**)&Ql, g_Ql);
    cudaGetSymbolAddress((void**)&Kh, g_Kh);   cudaGetSymbolAddress((void**)&Kl, g_Kl);
    cudaGetSymbolAddress((void**)&Vth, g_Vth); cudaGetSymbolAddress((void**)&Vtl, g_Vtl);
    cudaGetSymbolAddress((void**)&Sc, g_Sc);

    cudaFuncSetAttribute((const void*)gemm_mma<0, 3>, cudaFuncAttributeMaxDynamicSharedMemorySize, SMEM_BYTES);
    cudaFuncSetAttribute((const void*)gemm_mma<0, 2>, cudaFuncAttributeMaxDynamicSharedMemorySize, SMEM_BYTES);
    cudaFuncSetAttribute((const void*)gemm_mma<1, 3>, cudaFuncAttributeMaxDynamicSharedMemorySize, SMEM_BYTES);
    cudaFuncSetAttribute((const void*)gemm_mma<2, 3>, cudaFuncAttributeMaxDynamicSharedMemorySize, SMEM_BYTES);

    // 1. Splits (single fused launch)
    split4_kernel<<<2048, 256>>>(x, Wq, Wk, Wv, xh, xl, Wqh, Wql, Wkh, Wkl, Wvh, Wvl);

    // 2. Projections (NT, 3-product): Q, K normal; V transposed.
    const dim3 gp(NDIM / BN, MDIM / BM);
    gemm_mma<1, 3><<<gp, 256, SMEM_BYTES>>>(xh, xl, NDIM, Wqh, Wql, NDIM, NDIM, 1.f,
                                            nullptr, 0, Qh, Ql, NDIM, bq);
    gemm_mma<1, 3><<<gp, 256, SMEM_BYTES>>>(xh, xl, NDIM, Wkh, Wkl, NDIM, NDIM, 1.f,
                                            nullptr, 0, Kh, Kl, NDIM, bk);
    gemm_mma<2, 3><<<gp, 256, SMEM_BYTES>>>(xh, xl, NDIM, Wvh, Wvl, NDIM, NDIM, 1.f,
                                            nullptr, 0, Vth, Vtl, MDIM, bv);

    // 3. Attention, chunked over query rows.
    for (int c = 0; c < NCH; c++) {
        const size_t qoff = (size_t)c * CHUNK * NDIM;

        // Sc = (Qc @ K^T) / 32  (fp32 out; 2-product: Q split, K hi-only)
        const dim3 gs(MDIM / BN, CHUNK / BM);
        gemm_mma<0, 2><<<gs, 256, SMEM_BYTES>>>(Qh + qoff, Ql + qoff, NDIM,
                                                Kh, Kh, NDIM, NDIM, 0.03125f,
                                                Sc, MDIM, nullptr, nullptr, 0, nullptr);

        // softmax + in-place fp16 hi/lo split of P
        softmax_split_kernel<<<CHUNK, 256>>>(Sc);

        // out_c = P @ V  (NT with Vt rows indexed by N; 2-product: P split, V hi)
        const dim3 go(NDIM / BN, CHUNK / BM);
        gemm_mma<0, 2><<<go, 256, SMEM_BYTES>>>((const __half*)Sc,
                                                (const __half*)Sc + MDIM,
                                                (size_t)2 * MDIM,
                                                Vth, Vth, MDIM, MDIM, 1.f,
                                                out + qoff, NDIM, nullptr, nullptr, 0, nullptr);
    }
}

// round 17
// speedup vs baseline: 1.2289x; 1.2289x over previous
#include <cuda_runtime.h>
#include <cuda_fp16.h>
#include <cstdint>

#define MDIM 8192
#define NDIM 1024
#define CHUNK 4096
#define NCH (MDIM / CHUNK)

// ---------------------------------------------------------------------------
// Static scratch (no allocation allowed). Total ~268 MB.
// ---------------------------------------------------------------------------
__device__ __half g_xh[(size_t)MDIM * NDIM], g_xl[(size_t)MDIM * NDIM];
__device__ __half g_Wqh[(size_t)NDIM * NDIM], g_Wql[(size_t)NDIM * NDIM];
__device__ __half g_Wkh[(size_t)NDIM * NDIM], g_Wkl[(size_t)NDIM * NDIM];
__device__ __half g_Wvh[(size_t)NDIM * NDIM], g_Wvl[(size_t)NDIM * NDIM];
__device__ __half g_Qh[(size_t)MDIM * NDIM], g_Ql[(size_t)MDIM * NDIM];
__device__ __half g_Kh[(size_t)MDIM * NDIM], g_Kl[(size_t)MDIM * NDIM];
__device__ __half g_Vth[(size_t)NDIM * MDIM], g_Vtl[(size_t)NDIM * MDIM]; // V^T
__device__ float g_Sc[(size_t)CHUNK * MDIM];

// ---------------------------------------------------------------------------
// Portable (sm_80+) tensor-core primitives — NO tcgen05 (harness targets base
// sm_100, which rejects arch-specific instructions).
// ---------------------------------------------------------------------------
__device__ __forceinline__ uint32_t smem_u32(const void* p) {
    uint32_t a;
    asm("{ .reg .u64 t; cvta.to.shared.u64 t, %1; cvt.u32.u64 %0, t; }"
        : "=r"(a) : "l"(p));
    return a;
}

__device__ __forceinline__ void ldsm_x4(uint32_t* r, uint32_t addr) {
    asm volatile("ldmatrix.sync.aligned.m8n8.x4.shared.b16 {%0,%1,%2,%3}, [%4];"
                 : "=r"(r[0]), "=r"(r[1]), "=r"(r[2]), "=r"(r[3]) : "r"(addr));
}

__device__ __forceinline__ void mma_f16(float* d, const uint32_t* a,
                                        uint32_t b0, uint32_t b1) {
    asm volatile(
        "mma.sync.aligned.m16n8k16.row.col.f32.f16.f16.f32 "
        "{%0,%1,%2,%3}, {%4,%5,%6,%7}, {%8,%9}, {%0,%1,%2,%3};"
        : "+f"(d[0]), "+f"(d[1]), "+f"(d[2]), "+f"(d[3])
        : "r"(a[0]), "r"(a[1]), "r"(a[2]), "r"(a[3]), "r"(b0), "r"(b1));
}

#define CP_ASYNC16(dst, src) \
    asm volatile("cp.async.cg.shared.global [%0], [%1], 16;" \
                 :: "r"(dst), "l"(src) : "memory")
#define CP_COMMIT() asm volatile("cp.async.commit_group;" ::: "memory")
#define CP_WAIT0()  asm volatile("cp.async.wait_group 0;" ::: "memory")

// ---------------------------------------------------------------------------
// GEMM (NT), fp16 split-precision, fp32 accumulate via mma.sync.m16n8k16.
//   NPROD==3: C = Ahi·Bhi^T + Ahi·Blo^T + Alo·Bhi^T  (err ~2^-22)
//   NPROD==2: C = Ahi·Bhi^T + Alo·Bhi^T              (B hi-only, err ~2^-12)
//   NPROD==1: C = Ahi·Bhi^T                          (both hi-only)
// Tiles per stage: NPROD==1 -> 2 (Ahi,Bhi); ==2 -> 3; ==3 -> 4.
//   EPI 0: Cf[row*Csr+col] = acc * alpha
//   EPI 1: v = acc + bias[col]; Chi/Clo[row*Cosr+col] = hi/lo(v)
//   EPI 2: v = acc + bias[col]; Chi/Clo[col*Cosr+row] = hi/lo(v)  (transposed)
// BM=BN=128, BK=32, 256 threads (8 warps of 32x64), 2-stage cp.async pipeline,
// 2 CTAs/SM.
// ---------------------------------------------------------------------------
constexpr int BM = 128, BN = 128, BK = 32;
constexpr int TSTR = 80;                  // smem bytes per tile row (bank-safe)
constexpr int TILE_B = 128 * TSTR;        // 10240 B per tile
constexpr int STAGE_B = 4 * TILE_B;       // Ahi, (Alo), Bhi, (Blo)
constexpr int SMEM_BYTES = 2 * STAGE_B;   // 81920 B; epilogue staging reuses it

template <int EPI, int NPROD>
__global__ __launch_bounds__(256, 2) void gemm_mma(
    const __half* __restrict__ Ahi, const __half* __restrict__ Alo, size_t Asr,
    const __half* __restrict__ Bhi, const __half* __restrict__ Blo, size_t Bsr,
    int Kdim, float alpha,
    float* __restrict__ Cf, size_t Csr,
    __half* __restrict__ Chi, __half* __restrict__ Clo, size_t Cosr,
    const float* __restrict__ bias)
{
    extern __shared__ char smem[];
    const uint32_t sb = smem_u32(smem);
    const int tid = threadIdx.x, lane = tid & 31, wid = tid >> 5;
    const int bm = blockIdx.y * BM, bn = blockIdx.x * BN;
    const int wm = (wid & 3) * 32, wn = (wid >> 2) * 64;

    float acc[2][8][4];
#pragma unroll
    for (int i = 0; i < 2; i++)
#pragma unroll
        for (int j = 0; j < 8; j++)
#pragma unroll
            for (int q = 0; q < 4; q++) acc[i][j][q] = 0.f;

    const int S = Kdim / BK;

    // Stage loader: 2-4 tiles x 128 rows x 64B; 512 x 16B chunks per tile.
#define LOAD_STAGE(stg_u32, k0)                                                 \
    do {                                                                        \
        _Pragma("unroll")                                                       \
        for (int it = 0; it < 2; it++) {                                        \
            const int idx = tid + it * 256;                                     \
            const int r = idx >> 2, c = idx & 3;                                \
            const char* ga = (const char*)(Ahi + (size_t)(bm + r) * Asr + (k0)) + c * 16; \
            const char* gc = (const char*)(Bhi + (size_t)(bn + r) * Bsr + (k0)) + c * 16; \
            const uint32_t o = (uint32_t)(r * TSTR + c * 16);                   \
            CP_ASYNC16((stg_u32) + 0 * TILE_B + o, ga);                         \
            CP_ASYNC16((stg_u32) + 2 * TILE_B + o, gc);                         \
            if (NPROD >= 2) {                                                   \
                const char* gb = (const char*)(Alo + (size_t)(bm + r) * Asr + (k0)) + c * 16; \
                CP_ASYNC16((stg_u32) + 1 * TILE_B + o, gb);                     \
            }                                                                   \
            if (NPROD == 3) {                                                   \
                const char* gd = (const char*)(Blo + (size_t)(bn + r) * Bsr + (k0)) + c * 16; \
                CP_ASYNC16((stg_u32) + 3 * TILE_B + o, gd);                     \
            }                                                                   \
        }                                                                       \
    } while (0)

    LOAD_STAGE(sb, 0);
    CP_COMMIT();

    // ldmatrix lane decomposition: 4 groups of 8 lanes -> 4 8x8 tiles
    const int lr = lane & 7;
    const int lg1 = (lane >> 3) & 1;   // +8 rows
    const int lg2 = lane >> 4;         // +8 cols (16 bytes)

    for (int s = 0; s < S; s++) {
        CP_WAIT0();
        __syncthreads();
        const uint32_t sc = sb + (uint32_t)((s & 1) * STAGE_B);
        if (s + 1 < S) {
            const uint32_t sn = sb + (uint32_t)(((s + 1) & 1) * STAGE_B);
            LOAD_STAGE(sn, (s + 1) * BK);
            CP_COMMIT();
        }

#pragma unroll
        for (int ks = 0; ks < 2; ks++) {
            const int kb = ks * 32;    // byte offset of this k16 step

            uint32_t ah[2][4], al[2][4];
#pragma unroll
            for (int mt = 0; mt < 2; mt++) {
                const uint32_t aaddr = sc +
                    (uint32_t)((wm + mt * 16 + lr + lg1 * 8) * TSTR + kb + lg2 * 16);
                ldsm_x4(ah[mt], aaddr);
                if (NPROD >= 2) ldsm_x4(al[mt], aaddr + TILE_B);
            }
#pragma unroll
            for (int nt = 0; nt < 4; nt++) {
                uint32_t bh[4], bl[4];
                const uint32_t baddr = sc + 2 * TILE_B +
                    (uint32_t)((wn + nt * 16 + lr + lg1 * 8) * TSTR + kb + lg2 * 16);
                ldsm_x4(bh, baddr);
                if (NPROD == 3) ldsm_x4(bl, baddr + TILE_B);
#pragma unroll
                for (int mt = 0; mt < 2; mt++) {
#pragma unroll
                    for (int h = 0; h < 2; h++) {
                        float* d = acc[mt][nt * 2 + h];
                        mma_f16(d, ah[mt], bh[h], bh[2 + h]);          // hi*hi
                        if (NPROD == 3)
                            mma_f16(d, ah[mt], bl[h], bl[2 + h]);      // hi*lo
                        if (NPROD >= 2)
                            mma_f16(d, al[mt], bh[h], bh[2 + h]);      // lo*hi
                    }
                }
            }
        }
        __syncthreads();
    }

    // ---- Epilogue: regs -> padded SMEM staging -> coalesced global stores ----
    float* stg = (float*)smem;   // [128][129] fp32 (tile buffers now dead)
#pragma unroll
    for (int mt = 0; mt < 2; mt++)
#pragma unroll
        for (int nf = 0; nf < 8; nf++) {
            const int r0 = wm + mt * 16 + (lane >> 2);
            const int cl = wn + nf * 8 + (lane & 3) * 2;
            float v0 = acc[mt][nf][0], v1 = acc[mt][nf][1];
            float v2 = acc[mt][nf][2], v3 = acc[mt][nf][3];
            if (EPI == 0) {
                v0 *= alpha; v1 *= alpha; v2 *= alpha; v3 *= alpha;
            } else {
                const float b0 = bias[bn + cl], b1 = bias[bn + cl + 1];
                v0 += b0; v1 += b1; v2 += b0; v3 += b1;
            }
            stg[r0 * 129 + cl] = v0;
            stg[r0 * 129 + cl + 1] = v1;
            stg[(r0 + 8) * 129 + cl] = v2;
            stg[(r0 + 8) * 129 + cl + 1] = v3;
        }
    __syncthreads();

    if (EPI == 0) {
        for (int i = tid; i < BM * 32; i += 256) {
            const int r = i >> 5, q = (i & 31) * 4;
            float4 v;
            v.x = stg[r * 129 + q + 0];
            v.y = stg[r * 129 + q + 1];
            v.z = stg[r * 129 + q + 2];
            v.w = stg[r * 129 + q + 3];
            *(float4*)(Cf + (size_t)(bm + r) * Csr + bn + q) = v;
        }
    } else {
        for (int i = tid; i < BM * 16; i += 256) {
            const int a0 = i >> 4, g = (i & 15) * 8;
            alignas(16) __half hh[8], ll[8];
#pragma unroll
            for (int j = 0; j < 8; j++) {
                const float v = (EPI == 1) ? stg[a0 * 129 + g + j]
                                           : stg[(g + j) * 129 + a0];
                const __half h = __float2half(v);
                hh[j] = h;
                ll[j] = __float2half(v - __half2float(h));
            }
            const size_t off = (EPI == 1) ? ((size_t)(bm + a0) * Cosr + bn + g)
                                          : ((size_t)(bn + a0) * Cosr + bm + g);
            *(uint4*)(Chi + off) = *(const uint4*)hh;
            *(uint4*)(Clo + off) = *(const uint4*)ll;
        }
    }
#undef LOAD_STAGE
}

// ---------------------------------------------------------------------------
// Fused fp32 -> fp16 hi/lo split for x, Wq, Wk, Wv in ONE launch.
// ---------------------------------------------------------------------------
__global__ void split4_kernel(const float* __restrict__ x,
                              const float* __restrict__ wq,
                              const float* __restrict__ wk,
                              const float* __restrict__ wv,
                              __half* __restrict__ xh, __half* __restrict__ xl,
                              __half* __restrict__ qh, __half* __restrict__ ql,
                              __half* __restrict__ kh, __half* __restrict__ kl,
                              __half* __restrict__ vh, __half* __restrict__ vl)
{
    const size_t NX = (size_t)MDIM * NDIM;        // 8M
    const size_t NW = (size_t)NDIM * NDIM;        // 1M
    const size_t total = NX + 3 * NW;
    for (size_t i = (size_t)blockIdx.x * blockDim.x + threadIdx.x; i < total;
         i += (size_t)gridDim.x * blockDim.x) {
        const float* s; __half* h; __half* l; size_t j;
        if (i < NX)               { s = x;  h = xh; l = xl; j = i; }
        else if (i < NX + NW)     { s = wq; h = qh; l = ql; j = i - NX; }
        else if (i < NX + 2 * NW) { s = wk; h = kh; l = kl; j = i - NX - NW; }
        else                      { s = wv; h = vh; l = vl; j = i - NX - 2 * NW; }
        const float v = s[j];
        const __half hh = __float2half(v);
        h[j] = hh;
        l[j] = __float2half(v - __half2float(hh));
    }
}

// ---------------------------------------------------------------------------
// Row softmax over fp32 rows of length MDIM; writes P back IN PLACE as fp16
// hi (first half of the row). P-lo is no longer consumed (1-product PV), so
// it is not written. One block per row.
// ---------------------------------------------------------------------------
__global__ __launch_bounds__(256) void softmax_split_kernel(float* __restrict__ S)
{
    __shared__ float red[8];
    __shared__ float bcast;
    const int t = threadIdx.x;
    float* row = S + (size_t)blockIdx.x * MDIM;

    float v[32];
    float m = -1e30f;
#pragma unroll
    for (int i = 0; i < 32; i++) {
        v[i] = row[t + 256 * i];
        m = fmaxf(m, v[i]);
    }
#pragma unroll
    for (int o = 16; o; o >>= 1) m = fmaxf(m, __shfl_xor_sync(0xffffffffu, m, o));
    if ((t & 31) == 0) red[t >> 5] = m;
    __syncthreads();
    if (t < 32) {
        float mm = (t < 8) ? red[t] : -1e30f;
#pragma unroll
        for (int o = 4; o; o >>= 1) mm = fmaxf(mm, __shfl_xor_sync(0xffffffffu, mm, o));
        if (t == 0) bcast = mm;
    }
    __syncthreads();
    m = bcast;

    float ssum = 0.f;
    const float LOG2E = 1.4426950408889634f;
#pragma unroll
    for (int i = 0; i < 32; i++) {
        v[i] = exp2f((v[i] - m) * LOG2E);
        ssum += v[i];
    }
#pragma unroll
    for (int o = 16; o; o >>= 1) ssum += __shfl_xor_sync(0xffffffffu, ssum, o);
    __syncthreads();
    if ((t & 31) == 0) red[t >> 5] = ssum;
    __syncthreads();
    if (t < 32) {
        float ss = (t < 8) ? red[t] : 0.f;
#pragma unroll
        for (int o = 4; o; o >>= 1) ss += __shfl_xor_sync(0xffffffffu, ss, o);
        if (t == 0) bcast = ss;
    }
    __syncthreads();
    const float inv = 1.0f / bcast;

    __half* hrow = (__half*)row;
#pragma unroll
    for (int i = 0; i < 32; i++) {
        hrow[t + 256 * i] = __float2half(v[i] * inv);
    }
}

// ---------------------------------------------------------------------------
// Launch
// ---------------------------------------------------------------------------
extern "C" void kernel_launch(void* const* d_in, const int* in_sizes, int n_in,
                              void* d_out, int out_size)
{
    const float* x  = (const float*)d_in[0];
    const float* Wq = (const float*)d_in[1];
    const float* bq = (const float*)d_in[2];
    const float* Wk = (const float*)d_in[3];
    const float* bk = (const float*)d_in[4];
    const float* Wv = (const float*)d_in[5];
    const float* bv = (const float*)d_in[6];
    float* out = (float*)d_out;

    __half *xh, *xl, *Wqh, *Wql, *Wkh, *Wkl, *Wvh, *Wvl;
    __half *Qh, *Ql, *Kh, *Kl, *Vth, *Vtl;
    float* Sc;
    cudaGetSymbolAddress((void**)&xh, g_xh);   cudaGetSymbolAddress((void**)&xl, g_xl);
    cudaGetSymbolAddress((void**)&Wqh, g_Wqh); cudaGetSymbolAddress((void**)&Wql, g_Wql);
    cudaGetSymbolAddress((void**)&Wkh, g_Wkh); cudaGetSymbolAddress((void**)&Wkl, g_Wkl);
    cudaGetSymbolAddress((void**)&Wvh, g_Wvh); cudaGetSymbolAddress((void**)&Wvl, g_Wvl);
    cudaGetSymbolAddress((void**)&Qh, g_Qh);   cudaGetSymbolAddress((void**)&Ql, g_Ql);
    cudaGetSymbolAddress((void**)&Kh, g_Kh);   cudaGetSymbolAddress((void**)&Kl, g_Kl);
    cudaGetSymbolAddress((void**)&Vth, g_Vth); cudaGetSymbolAddress((void**)&Vtl, g_Vtl);
    cudaGetSymbolAddress((void**)&Sc, g_Sc);

    cudaFuncSetAttribute((const void*)gemm_mma<0, 2>, cudaFuncAttributeMaxDynamicSharedMemorySize, SMEM_BYTES);
    cudaFuncSetAttribute((const void*)gemm_mma<0, 1>, cudaFuncAttributeMaxDynamicSharedMemorySize, SMEM_BYTES);
    cudaFuncSetAttribute((const void*)gemm_mma<1, 3>, cudaFuncAttributeMaxDynamicSharedMemorySize, SMEM_BYTES);
    cudaFuncSetAttribute((const void*)gemm_mma<2, 3>, cudaFuncAttributeMaxDynamicSharedMemorySize, SMEM_BYTES);

    // 1. Splits (single fused launch)
    split4_kernel<<<2048, 256>>>(x, Wq, Wk, Wv, xh, xl, Wqh, Wql, Wkh, Wkl, Wvh, Wvl);

    // 2. Projections (NT, 3-product): Q, K normal; V transposed.
    const dim3 gp(NDIM / BN, MDIM / BM);
    gemm_mma<1, 3><<<gp, 256, SMEM_BYTES>>>(xh, xl, NDIM, Wqh, Wql, NDIM, NDIM, 1.f,
                                            nullptr, 0, Qh, Ql, NDIM, bq);
    gemm_mma<1, 3><<<gp, 256, SMEM_BYTES>>>(xh, xl, NDIM, Wkh, Wkl, NDIM, NDIM, 1.f,
                                            nullptr, 0, Kh, Kl, NDIM, bk);
    gemm_mma<2, 3><<<gp, 256, SMEM_BYTES>>>(xh, xl, NDIM, Wvh, Wvl, NDIM, NDIM, 1.f,
                                            nullptr, 0, Vth, Vtl, MDIM, bv);

    // 3. Attention, chunked over query rows.
    for (int c = 0; c < NCH; c++) {
        const size_t qoff = (size_t)c * CHUNK * NDIM;

        // Sc = (Qc @ K^T) / 32  (fp32 out; 2-product: Q split, K hi-only)
        const dim3 gs(MDIM / BN, CHUNK / BM);
        gemm_mma<0, 2><<<gs, 256, SMEM_BYTES>>>(Qh + qoff, Ql + qoff, NDIM,
                                                Kh, Kh, NDIM, NDIM, 0.03125f,
                                                Sc, MDIM, nullptr, nullptr, 0, nullptr);

        // softmax + in-place fp16 split of P (hi only)
        softmax_split_kernel<<<CHUNK, 256>>>(Sc);

        // out_c = P @ V  (NT with Vt rows indexed by N; 1-product: P hi, V hi)
        const dim3 go(NDIM / BN, CHUNK / BM);
        gemm_mma<0, 1><<<go, 256, SMEM_BYTES>>>((const __half*)Sc,
                                                (const __half*)Sc,
                                                (size_t)2 * MDIM,
                                                Vth, Vth, MDIM, MDIM, 1.f,
                                                out + qoff, NDIM, nullptr, nullptr, 0, nullptr);
    }
}